// round 13
// baseline (speedup 1.0000x reference)
#include <cuda_runtime.h>
#include <math.h>

// Shapes
#define NB 256            // batch
#define NF 4              // frames
#define PIX4 9408         // 16B-vectors per frame (3*112*112/4)
#define TPB 256
#define CH 4096           // vectors per block: 256*9408 = 588*4096 exactly
#define GRID 588          // <= 592 (148 SMs * 4 CTAs) — exactly one wave
#define NSTEP 16          // CH / TPB

// Scratch. g_part/g_neq: zero at process start; epilogue re-zeroes after use.
__device__ float g_part[NB * 3];
__device__ int   g_neq[NB];
__device__ float g_cos[NB * 3];
__device__ int   g_ctr;

// ---- packed f32x2 helpers (sm_100+) ----------------------------------------
static __device__ __forceinline__ unsigned long long pk2(unsigned x, unsigned y) {
    unsigned long long r;
    asm("mov.b64 %0, {%1,%2};" : "=l"(r) : "r"(x), "r"(y));
    return r;
}
static __device__ __forceinline__ unsigned long long fma2(unsigned long long a,
                                                          unsigned long long b,
                                                          unsigned long long c) {
    unsigned long long d;
    asm("fma.rn.f32x2 %0, %1, %2, %3;" : "=l"(d) : "l"(a), "l"(b), "l"(c));
    return d;
}
static __device__ __forceinline__ unsigned long long mul2(unsigned long long a,
                                                          unsigned long long b) {
    unsigned long long d;
    asm("mul.rn.f32x2 %0, %1, %2;" : "=l"(d) : "l"(a), "l"(b));
    return d;
}
static __device__ __forceinline__ unsigned long long add2(unsigned long long a,
                                                          unsigned long long b) {
    unsigned long long d;
    asm("add.rn.f32x2 %0, %1, %2;" : "=l"(d) : "l"(a), "l"(b));
    return d;
}
static __device__ __forceinline__ float hsum2(unsigned long long a) {
    unsigned x, y;
    asm("mov.b64 {%0,%1}, %2;" : "=r"(x), "=r"(y) : "l"(a));
    return __uint_as_float(x) + __uint_as_float(y);
}

struct Acc {
    unsigned long long a0, a1, a2;   // packed f32x2 squared-diff sums (3 pairs)
    unsigned m0, m1, m2;             // raw XOR-OR words (nonzero => neq)
};

__device__ __forceinline__ void stepf(const uint4& q0, const uint4& q1,
                                      const uint4& q2, const uint4& q3, Acc& A) {
    const unsigned long long M1 = 0xBF800000BF800000ULL;  // {-1.f,-1.f}
    unsigned long long p0 = pk2(q0.x, q0.y), P0 = pk2(q0.z, q0.w);
    unsigned long long p1 = pk2(q1.x, q1.y), P1 = pk2(q1.z, q1.w);
    unsigned long long p2 = pk2(q2.x, q2.y), P2 = pk2(q2.z, q2.w);
    unsigned long long p3 = pk2(q3.x, q3.y), P3 = pk2(q3.z, q3.w);
    unsigned long long d, e;
    d = fma2(p0, M1, p1); e = fma2(P0, M1, P1);   // f1 - f0
    A.a0 = add2(A.a0, fma2(e, e, mul2(d, d)));
    d = fma2(p1, M1, p2); e = fma2(P1, M1, P2);   // f2 - f1
    A.a1 = add2(A.a1, fma2(e, e, mul2(d, d)));
    d = fma2(p2, M1, p3); e = fma2(P2, M1, P3);   // f3 - f2
    A.a2 = add2(A.a2, fma2(e, e, mul2(d, d)));
    // neq vs frame 0 (bitwise; input has no NaN / ±0 collisions)
    A.m0 |= (q1.x ^ q0.x) | (q1.y ^ q0.y) | (q1.z ^ q0.z) | (q1.w ^ q0.w);
    A.m1 |= (q2.x ^ q0.x) | (q2.y ^ q0.y) | (q2.z ^ q0.z) | (q2.w ^ q0.w);
    A.m2 |= (q3.x ^ q0.x) | (q3.y ^ q0.y) | (q3.z ^ q0.z) | (q3.w ^ q0.w);
}

__global__ void __launch_bounds__(TPB, 4)
fused_kernel(const uint4* __restrict__ img,
             const float* __restrict__ feat,
             const float* __restrict__ feat_norm,
             float* __restrict__ out) {
    __shared__ float sm7[7][TPB / 32];
    __shared__ unsigned long long smacc[6][TPB / 32];
    __shared__ int smn[TPB / 32];
    __shared__ int s_last;

    const int w = threadIdx.x >> 5;
    const int l = threadIdx.x & 31;

    // ---------------- feat prelude (blocks 0..255 only) -------------------
    if (blockIdx.x < NB) {
        const int b = blockIdx.x;
        const float* fb = feat + (size_t)b * (NF * 512);

        float n0 = 0.f, n1 = 0.f, n2 = 0.f, n3 = 0.f;
        float d01 = 0.f, d12 = 0.f, d23 = 0.f;
        #pragma unroll
        for (int k = 0; k < 2; k++) {
            int i = threadIdx.x + k * TPB;
            float a = fb[i];
            float c = fb[512 + i];
            float d = fb[1024 + i];
            float e = fb[1536 + i];
            n0 += a * a; n1 += c * c; n2 += d * d; n3 += e * e;
            d01 += a * c; d12 += c * d; d23 += d * e;
        }
        #pragma unroll
        for (int off = 16; off; off >>= 1) {
            n0  += __shfl_down_sync(0xffffffffu, n0,  off);
            n1  += __shfl_down_sync(0xffffffffu, n1,  off);
            n2  += __shfl_down_sync(0xffffffffu, n2,  off);
            n3  += __shfl_down_sync(0xffffffffu, n3,  off);
            d01 += __shfl_down_sync(0xffffffffu, d01, off);
            d12 += __shfl_down_sync(0xffffffffu, d12, off);
            d23 += __shfl_down_sync(0xffffffffu, d23, off);
        }
        if (l == 0) {
            sm7[0][w] = n0;  sm7[1][w] = n1;  sm7[2][w] = n2;  sm7[3][w] = n3;
            sm7[4][w] = d01; sm7[5][w] = d12; sm7[6][w] = d23;
        }
        __syncthreads();
        if (threadIdx.x == 0) {
            float v[7];
            #pragma unroll
            for (int j = 0; j < 7; j++) {
                float s = 0.f;
                #pragma unroll
                for (int k = 0; k < TPB / 32; k++) s += sm7[j][k];
                v[j] = s;
            }
            float na[4];
            #pragma unroll
            for (int j = 0; j < 4; j++) na[j] = fmaxf(sqrtf(v[j]), 1e-8f);
            #pragma unroll
            for (int j = 0; j < 3; j++)
                g_cos[b * 3 + j] = v[4 + j] / (na[j] * na[j + 1]);

            const float fn0 = feat_norm[b * NF];     // feat_norm[b,0,0]
            const bool cond = fn0 > 0.0f;            // TAO = 0
            const float wgt = 1.0f / (expf(fn0) + 1e-10f);
            out[1 + b] = cond ? wgt : 0.0f;          // also encodes cond (wgt>0)
        }
        __syncthreads();
    }

    // ---------------- img chunk: rotated software pipeline ----------------
    {
        const int start = blockIdx.x * CH;
        const int batch_lo = start / PIX4;
        const int boundary = (batch_lo + 1) * PIX4;
        const bool crosses = boundary < start + CH;
        const uint4* baseA = img + (size_t)3 * batch_lo * PIX4;
        const uint4* baseB = baseA + 3 * PIX4;

        Acc A = {0, 0, 0, 0, 0, 0};
        Acc B = {0, 0, 0, 0, 0, 0};

        // prologue: step 0 loads
        int g = start + threadIdx.x;
        bool hi = g >= boundary;
        const uint4* p = hi ? baseB : baseA;
        uint4 c0 = __ldcs(p + g);
        uint4 c1 = __ldcs(p + g + PIX4);
        uint4 c2 = __ldcs(p + g + 2 * PIX4);
        uint4 c3 = __ldcs(p + g + 3 * PIX4);

        #pragma unroll
        for (int k = 1; k < NSTEP; k++) {
            const int gn = start + k * TPB + threadIdx.x;
            const bool hin = gn >= boundary;
            const uint4* pn = hin ? baseB : baseA;
            // issue next step's loads BEFORE computing current step
            uint4 n0 = __ldcs(pn + gn);
            uint4 n1 = __ldcs(pn + gn + PIX4);
            uint4 n2 = __ldcs(pn + gn + 2 * PIX4);
            uint4 n3 = __ldcs(pn + gn + 3 * PIX4);

            if (hi) stepf(c0, c1, c2, c3, B);
            else    stepf(c0, c1, c2, c3, A);

            c0 = n0; c1 = n1; c2 = n2; c3 = n3; hi = hin;
        }
        if (hi) stepf(c0, c1, c2, c3, B);
        else    stepf(c0, c1, c2, c3, A);

        // Fused block reduction: 6 packed sums + packed neq masks.
        int nqp = ((A.m0 ? 1 : 0) | (A.m1 ? 2 : 0) | (A.m2 ? 4 : 0)) |
                  (((B.m0 ? 1 : 0) | (B.m1 ? 2 : 0) | (B.m2 ? 4 : 0)) << 16);
        #pragma unroll
        for (int off = 16; off; off >>= 1) {
            A.a0 = add2(A.a0, __shfl_down_sync(0xffffffffu, A.a0, off));
            A.a1 = add2(A.a1, __shfl_down_sync(0xffffffffu, A.a1, off));
            A.a2 = add2(A.a2, __shfl_down_sync(0xffffffffu, A.a2, off));
            B.a0 = add2(B.a0, __shfl_down_sync(0xffffffffu, B.a0, off));
            B.a1 = add2(B.a1, __shfl_down_sync(0xffffffffu, B.a1, off));
            B.a2 = add2(B.a2, __shfl_down_sync(0xffffffffu, B.a2, off));
            nqp |= __shfl_down_sync(0xffffffffu, nqp, off);
        }
        if (l == 0) {
            smacc[0][w] = A.a0; smacc[1][w] = A.a1; smacc[2][w] = A.a2;
            smacc[3][w] = B.a0; smacc[4][w] = B.a1; smacc[5][w] = B.a2;
            smn[w] = nqp;
        }
        __syncthreads();
        if (threadIdx.x == 0) {
            unsigned long long vv[6];
            int nq = 0;
            #pragma unroll
            for (int j = 0; j < 6; j++) {
                unsigned long long s = smacc[j][0];
                #pragma unroll
                for (int k = 1; k < TPB / 32; k++) s = add2(s, smacc[j][k]);
                vv[j] = s;
            }
            #pragma unroll
            for (int k = 0; k < TPB / 32; k++) nq |= smn[k];

            atomicAdd(&g_part[batch_lo * 3 + 0], hsum2(vv[0]));
            atomicAdd(&g_part[batch_lo * 3 + 1], hsum2(vv[1]));
            atomicAdd(&g_part[batch_lo * 3 + 2], hsum2(vv[2]));
            atomicOr(&g_neq[batch_lo], nq & 0x7);
            if (crosses) {
                const int bh = batch_lo + 1;
                atomicAdd(&g_part[bh * 3 + 0], hsum2(vv[3]));
                atomicAdd(&g_part[bh * 3 + 1], hsum2(vv[4]));
                atomicAdd(&g_part[bh * 3 + 2], hsum2(vv[5]));
                atomicOr(&g_neq[bh], (nq >> 16) & 0x7);
            }
        }
    }

    // ---------------- elect last-finished block for the epilogue ----------
    __syncthreads();
    if (threadIdx.x == 0) {
        __threadfence();
        int old = atomicAdd(&g_ctr, 1);
        s_last = (old == GRID - 1) ? 1 : 0;
    }
    __syncthreads();
    if (!s_last) return;

    __threadfence();  // acquire: all other blocks' atomics/stores visible

    // thread b handles batch b (256 threads == NB)
    const int b = threadIdx.x;
    float pen = 0.0f;
    {
        const float outw = out[1 + b];   // cond ? wgt : 0
        const float dsq[3] = {g_part[b * 3 + 0], g_part[b * 3 + 1], g_part[b * 3 + 2]};
        const int nqm = g_neq[b];
        #pragma unroll
        for (int j = 0; j < 3; j++) {
            float img_diff = sqrtf(dsq[j]) + 1e-10f;
            float ratio = (1.0f - g_cos[b * 3 + j]) / img_diff;  // LIP = 0
            float term = fmaxf(ratio, 0.0f) * outw;              // SQUARED = false
            if ((nqm >> j) & 1) pen += term;                     // outw==0 covers !cond
        }
    }

    // Reset scratch for the next graph replay (deterministic state).
    g_part[b * 3 + 0] = 0.f;
    g_part[b * 3 + 1] = 0.f;
    g_part[b * 3 + 2] = 0.f;
    g_neq[b] = 0;

    #pragma unroll
    for (int off = 16; off; off >>= 1)
        pen += __shfl_down_sync(0xffffffffu, pen, off);

    __shared__ float smr[TPB / 32];
    if (l == 0) smr[w] = pen;
    __syncthreads();
    if (threadIdx.x == 0) {
        float s = 0.f;
        #pragma unroll
        for (int k = 0; k < TPB / 32; k++) s += smr[k];
        out[0] = s * (1.0f / (float)NB);   // LAMB_LIP = 1
        g_ctr = 0;                          // reset for next replay
    }
}

extern "C" void kernel_launch(void* const* d_in, const int* in_sizes, int n_in,
                              void* d_out, int out_size) {
    const uint4* img = (const uint4*)d_in[0];
    const float* feat = (const float*)d_in[1];
    const float* feat_norm = (const float*)d_in[2];
    float* out = (float*)d_out;

    fused_kernel<<<GRID, TPB>>>(img, feat, feat_norm, out);
}